// round 1
// baseline (speedup 1.0000x reference)
#include <cuda_runtime.h>
#include <cuda_bf16.h>

// Problem constants
#define BATCH 8
#define CHAN  256
#define HEADS 8
#define DHEAD 32
#define IH    32
#define IW    32
#define NTOK  1024           // IH*IW
#define NPER  262144         // CHAN*NTOK (elements per sample per projection)
#define WSZ   (9*256*256)    // one conv weight, transposed
#define BIASN 3969           // (2*32-1)^2

// ---------------- scratch (device globals; no allocation) ----------------
__device__ float g_wT[3][WSZ];            // [proj][tap*256*256]  tap-major, ic, oc
__device__ float g_woT[256*256];          // [c][o]
__device__ float g_act[3][BATCH*NPER];    // conv out -> (in place) GN+GELU activations
__device__ float g_part[3][BATCH][32][2]; // per-row (sum, sumsq) GN partials
__device__ float g_attn[BATCH*NPER];      // attention output, [b][c][n]

// ---------------- 1) weight transposes ----------------
__global__ void transpose_w_kernel(const float* __restrict__ wq,
                                   const float* __restrict__ wk,
                                   const float* __restrict__ wv,
                                   const float* __restrict__ wo) {
    int p = blockIdx.y;
    int e = blockIdx.x * 256 + threadIdx.x;
    if (p < 3) {
        if (e < WSZ) {
            const float* w = (p == 0) ? wq : (p == 1) ? wk : wv;
            int oc = e & 255;
            int ic = (e >> 8) & 255;
            int t  = e >> 16;              // 0..8  (ky*3+kx)
            g_wT[p][e] = w[oc * 2304 + ic * 9 + t];
        }
    } else {
        if (e < 256 * 256) {
            int o = e & 255;
            int c = e >> 8;
            g_woT[e] = wo[o * 256 + c];    // g_woT[c*256+o]
        }
    }
}

// ---------------- 2) direct 3x3 conv, fused GN partial stats ----------------
// grid: (32 rows, 8 batch, 3 proj), block: 256 threads (one output channel each)
__global__ void conv3x3_kernel(const float* __restrict__ x) {
    const int hrow = blockIdx.x;
    const int b    = blockIdx.y;
    const int p    = blockIdx.z;
    const int oc   = threadIdx.x;

    __shared__ float s_in[64][3][34];   // ic-chunk x 3 rows x padded width
    __shared__ float s_r1[256];
    __shared__ float s_r2[256];

    float acc[32];
#pragma unroll
    for (int px = 0; px < 32; px++) acc[px] = 0.f;

    const float* wT = g_wT[p];

    for (int c0 = 0; c0 < 256; c0 += 64) {
        // cooperative load of 64 input channels x 3 rows (zero-padded)
        for (int e = threadIdx.x; e < 64 * 3 * 34; e += 256) {
            int ic = e / 102;
            int r  = e - ic * 102;
            int ky = r / 34;
            int wc = r - ky * 34;
            int wi = wc - 1;
            int hi = hrow + ky - 1;
            float v = 0.f;
            if ((unsigned)wi < 32u && (unsigned)hi < 32u)
                v = x[((b * 256 + c0 + ic) * 32 + hi) * 32 + wi];
            s_in[ic][ky][wc] = v;
        }
        __syncthreads();

        for (int ic = 0; ic < 64; ic++) {
            float wv[9];
#pragma unroll
            for (int t = 0; t < 9; t++)
                wv[t] = wT[(t * 256 + c0 + ic) * 256 + oc];
#pragma unroll
            for (int ky = 0; ky < 3; ky++) {
#pragma unroll
                for (int kx = 0; kx < 3; kx++) {
                    float wvv = wv[ky * 3 + kx];
#pragma unroll
                    for (int px = 0; px < 32; px++)
                        acc[px] += wvv * s_in[ic][ky][px + kx];
                }
            }
        }
        __syncthreads();
    }

    // store conv output (row of 32 pixels for this oc)
    float* outp = &g_act[p][((b * 256 + oc) * 32 + hrow) * 32];
#pragma unroll
    for (int px = 0; px < 32; px += 4) {
        float4 v4 = make_float4(acc[px], acc[px + 1], acc[px + 2], acc[px + 3]);
        *reinterpret_cast<float4*>(outp + px) = v4;
    }

    // GN partial stats for this (proj, b, row)
    float s = 0.f, sq = 0.f;
#pragma unroll
    for (int px = 0; px < 32; px++) { s += acc[px]; sq += acc[px] * acc[px]; }
    s_r1[oc] = s; s_r2[oc] = sq;
    __syncthreads();
    for (int st = 128; st > 0; st >>= 1) {
        if (oc < st) { s_r1[oc] += s_r1[oc + st]; s_r2[oc] += s_r2[oc + st]; }
        __syncthreads();
    }
    if (oc == 0) {
        g_part[p][b][hrow][0] = s_r1[0];
        g_part[p][b][hrow][1] = s_r2[0];
    }
}

// ---------------- 3) GroupNorm(1) + exact GELU, in place ----------------
// grid: (8 chunks, 8 batch, 3 proj), block 256
__global__ void gn_gelu_kernel(const float* __restrict__ gq, const float* __restrict__ bq,
                               const float* __restrict__ gk, const float* __restrict__ bk,
                               const float* __restrict__ gv, const float* __restrict__ bv) {
    const int chunk = blockIdx.x;
    const int b     = blockIdx.y;
    const int p     = blockIdx.z;
    const float* gg = (p == 0) ? gq : (p == 1) ? gk : gv;
    const float* bb = (p == 0) ? bq : (p == 1) ? bk : bv;

    __shared__ float s_mu, s_rs;
    if (threadIdx.x < 32) {
        float s  = g_part[p][b][threadIdx.x][0];
        float sq = g_part[p][b][threadIdx.x][1];
#pragma unroll
        for (int o = 16; o > 0; o >>= 1) {
            s  += __shfl_down_sync(0xffffffffu, s,  o);
            sq += __shfl_down_sync(0xffffffffu, sq, o);
        }
        if (threadIdx.x == 0) {
            float mu  = s / (float)NPER;
            float var = sq / (float)NPER - mu * mu;
            s_mu = mu;
            s_rs = rsqrtf(var + 1e-6f);
        }
    }
    __syncthreads();
    const float mu = s_mu, rs = s_rs;

    float* base = &g_act[p][b * NPER + chunk * 32768];
    for (int i = threadIdx.x; i < 8192; i += 256) {
        float4 v = reinterpret_cast<float4*>(base)[i];
        int c = (chunk * 32768 + i * 4) >> 10;
        float gc = gg[c], bc = bb[c];
        float t0 = (v.x - mu) * rs * gc + bc;
        float t1 = (v.y - mu) * rs * gc + bc;
        float t2 = (v.z - mu) * rs * gc + bc;
        float t3 = (v.w - mu) * rs * gc + bc;
        v.x = 0.5f * t0 * (1.0f + erff(t0 * 0.70710678118654752f));
        v.y = 0.5f * t1 * (1.0f + erff(t1 * 0.70710678118654752f));
        v.z = 0.5f * t2 * (1.0f + erff(t2 * 0.70710678118654752f));
        v.w = 0.5f * t3 * (1.0f + erff(t3 * 0.70710678118654752f));
        reinterpret_cast<float4*>(base)[i] = v;
    }
}

// ---------------- 4) flash attention with relative position bias ----------------
// grid: (8 q-tiles, 8 heads, 8 batch), block 128 (one query row per thread)
__global__ void attn_kernel(const float* __restrict__ bias_table) {
    const int q0  = blockIdx.x * 128;
    const int h   = blockIdx.y;
    const int b   = blockIdx.z;
    const int tid = threadIdx.x;

    __shared__ float s_bias[BIASN];
    __shared__ float s_k[32 * 128];
    __shared__ float s_v[32 * 128];

    for (int i = tid; i < BIASN; i += 128)
        s_bias[i] = bias_table[i * HEADS + h];

    const float* aq = &g_act[0][(b * 256 + h * DHEAD) * NTOK];
    const float* ak = &g_act[1][(b * 256 + h * DHEAD) * NTOK];
    const float* av = &g_act[2][(b * 256 + h * DHEAD) * NTOK];

    const int qi = q0 + tid;
    float q[DHEAD];
#pragma unroll
    for (int d = 0; d < DHEAD; d++) q[d] = aq[d * NTOK + qi];

    const int yi = qi >> 5, xi = qi & 31;

    float m = -1e30f, l = 0.f;
    float o[DHEAD];
#pragma unroll
    for (int d = 0; d < DHEAD; d++) o[d] = 0.f;

    for (int kt = 0; kt < 8; kt++) {
        const int k0 = kt * 128;
        __syncthreads();
        for (int e = tid; e < 4096; e += 128) {
            int d = e >> 7, j = e & 127;
            s_k[e] = ak[d * NTOK + k0 + j];
            s_v[e] = av[d * NTOK + k0 + j];
        }
        __syncthreads();

        for (int sub = 0; sub < 4; sub++) {
            float s[32];
#pragma unroll
            for (int jj = 0; jj < 32; jj++) {
                const int j  = sub * 32 + jj;
                const int kg = k0 + j;
                const int yj = kg >> 5, xj = kg & 31;
                const int idx = (yi - yj + 31) * 63 + (xi - xj + 31);
                float acc = s_bias[idx];
#pragma unroll
                for (int d = 0; d < DHEAD; d++)
                    acc += q[d] * s_k[d * 128 + j];
                s[jj] = acc;
            }
            float mn = m;
#pragma unroll
            for (int jj = 0; jj < 32; jj++) mn = fmaxf(mn, s[jj]);
            const float scale = __expf(m - mn);
            l *= scale;
#pragma unroll
            for (int d = 0; d < DHEAD; d++) o[d] *= scale;
#pragma unroll
            for (int jj = 0; jj < 32; jj++) {
                const float pw = __expf(s[jj] - mn);
                l += pw;
                const int j = sub * 32 + jj;
#pragma unroll
                for (int d = 0; d < DHEAD; d++)
                    o[d] += pw * s_v[d * 128 + j];
            }
            m = mn;
        }
    }

    const float inv = 1.f / l;
    float* ao = &g_attn[(b * 256 + h * DHEAD) * NTOK];
#pragma unroll
    for (int d = 0; d < DHEAD; d++)
        ao[d * NTOK + qi] = o[d] * inv;
}

// ---------------- 5) 1x1 output projection + bias ----------------
// grid: (32 n-tiles, 8 batch), block 256 (one output channel each)
__global__ void outproj_kernel(const float* __restrict__ bo, float* __restrict__ out) {
    const int nt = blockIdx.x;
    const int b  = blockIdx.y;
    const int oc = threadIdx.x;

    __shared__ float s_a[256 * 32];
    for (int e = oc; e < 8192; e += 256) {
        int c = e >> 5, px = e & 31;
        s_a[e] = g_attn[(b * 256 + c) * NTOK + nt * 32 + px];
    }
    __syncthreads();

    float acc[32];
#pragma unroll
    for (int px = 0; px < 32; px++) acc[px] = 0.f;

    for (int c = 0; c < 256; c++) {
        float wv = g_woT[c * 256 + oc];
#pragma unroll
        for (int px = 0; px < 32; px++)
            acc[px] += wv * s_a[c * 32 + px];
    }

    const float bb = bo[oc];
    float* op = out + (b * 256 + oc) * NTOK + nt * 32;
#pragma unroll
    for (int px = 0; px < 32; px += 4) {
        float4 v4 = make_float4(acc[px] + bb, acc[px + 1] + bb,
                                acc[px + 2] + bb, acc[px + 3] + bb);
        *reinterpret_cast<float4*>(op + px) = v4;
    }
}

// ---------------- launch ----------------
extern "C" void kernel_launch(void* const* d_in, const int* in_sizes, int n_in,
                              void* d_out, int out_size) {
    const float* x  = (const float*)d_in[0];
    const float* wq = (const float*)d_in[1];
    const float* wk = (const float*)d_in[2];
    const float* wv = (const float*)d_in[3];
    const float* gq = (const float*)d_in[4];
    const float* bq = (const float*)d_in[5];
    const float* gk = (const float*)d_in[6];
    const float* bk = (const float*)d_in[7];
    const float* gv = (const float*)d_in[8];
    const float* bv = (const float*)d_in[9];
    const float* bt = (const float*)d_in[10];
    const float* wo = (const float*)d_in[11];
    const float* bo = (const float*)d_in[12];
    float* out = (float*)d_out;

    transpose_w_kernel<<<dim3((WSZ + 255) / 256, 4), 256>>>(wq, wk, wv, wo);
    conv3x3_kernel<<<dim3(32, BATCH, 3), 256>>>(x);
    gn_gelu_kernel<<<dim3(8, BATCH, 3), 256>>>(gq, bq, gk, bk, gv, bv);
    attn_kernel<<<dim3(8, HEADS, BATCH), 128>>>(bt);
    outproj_kernel<<<dim3(32, BATCH), 256>>>(bo, out);
}

// round 3
// speedup vs baseline: 1.3026x; 1.3026x over previous
#include <cuda_runtime.h>
#include <cuda_bf16.h>

typedef unsigned long long ull;

// Problem constants
#define BATCH 8
#define CHAN  256
#define HEADS 8
#define DHEAD 32
#define IH    32
#define IW    32
#define NTOK  1024
#define NPER  262144
#define WSZ   (9*256*256)
#define BIASN 3969

// ---------------- scratch ----------------
__device__ __align__(16) float g_wT[3][WSZ];            // [proj][tap][ic][oc]
__device__ __align__(16) float g_woT[256*256];          // [c][o]
__device__ __align__(16) float g_act[3][BATCH*NPER];
__device__ __align__(16) float g_part[3][BATCH][32][2];
__device__ __align__(16) float g_attn[BATCH*NPER];

// ---------------- f32x2 helpers ----------------
__device__ __forceinline__ void ffma2(ull& d, ull a, ull b) {
    asm("fma.rn.f32x2 %0, %1, %2, %0;" : "+l"(d) : "l"(a), "l"(b));
}
__device__ __forceinline__ ull add2(ull a, ull b) {
    ull r; asm("add.rn.f32x2 %0, %1, %2;" : "=l"(r) : "l"(a), "l"(b)); return r;
}
__device__ __forceinline__ ull mul2(ull a, ull b) {
    ull r; asm("mul.rn.f32x2 %0, %1, %2;" : "=l"(r) : "l"(a), "l"(b)); return r;
}
__device__ __forceinline__ ull pack2(float a, float b) {
    ull u; asm("mov.b64 %0, {%1,%2};" : "=l"(u) : "f"(a), "f"(b)); return u;
}
__device__ __forceinline__ float lo2(ull u) { return __int_as_float((int)(unsigned)u); }
__device__ __forceinline__ float hi2(ull u) { return __int_as_float((int)(u >> 32)); }

// fast expf via exp2 poly (rel err ~1e-7); args here are always <= 0
__device__ __forceinline__ float fast_exp(float x) {
    float t  = fmaxf(x * 1.4426950408889634f, -126.0f);
    float fi = rintf(t);
    float f  = t - fi;
    float p  = 1.535336188319500e-4f;
    p = fmaf(p, f, 1.339887440266574e-3f);
    p = fmaf(p, f, 9.618437357674640e-3f);
    p = fmaf(p, f, 5.550332471162809e-2f);
    p = fmaf(p, f, 2.402264791363012e-1f);
    p = fmaf(p, f, 6.931472028550421e-1f);
    p = fmaf(p, f, 1.0f);
    return p * __int_as_float(((int)fi + 127) << 23);
}

// ---------------- 1) weight transposes ----------------
__global__ void transpose_w_kernel(const float* __restrict__ wq,
                                   const float* __restrict__ wk,
                                   const float* __restrict__ wv,
                                   const float* __restrict__ wo) {
    int p = blockIdx.y;
    int e = blockIdx.x * 256 + threadIdx.x;
    if (p < 3) {
        if (e < WSZ) {
            const float* w = (p == 0) ? wq : (p == 1) ? wk : wv;
            int oc = e & 255;
            int ic = (e >> 8) & 255;
            int t  = e >> 16;
            g_wT[p][e] = w[oc * 2304 + ic * 9 + t];
        }
    } else {
        if (e < 256 * 256) {
            int o = e & 255;
            int c = e >> 8;
            g_woT[e] = wo[o * 256 + c];
        }
    }
}

// ---------------- 2) 3x3 conv with f32x2, oc-pair per thread ----------------
// grid: (32 rows, 8 batch, 3 proj), block 128 (thread t -> oc 2t, 2t+1)
__global__ void conv3x3_kernel(const float* __restrict__ x) {
    const int hrow = blockIdx.x;
    const int b    = blockIdx.y;
    const int p    = blockIdx.z;
    const int t    = threadIdx.x;

    __shared__ __align__(16) float2 s_in2[32][3][34];   // dup-packed input, 26KB
    __shared__ float  s_r1[128];
    __shared__ float  s_r2[128];

    ull acc[32];
#pragma unroll
    for (int px = 0; px < 32; px++) acc[px] = 0ull;

    const ull* wp = reinterpret_cast<const ull*>(g_wT[p]);

    for (int c0 = 0; c0 < 256; c0 += 32) {
        // cooperative load: 32 ic x 3 rows x 34 cols, duplicated
        for (int e = t; e < 32 * 3 * 34; e += 128) {
            int ic = e / 102;
            int r  = e - ic * 102;
            int ky = r / 34;
            int wc = r - ky * 34;
            int wi = wc - 1;
            int hi = hrow + ky - 1;
            float v = 0.f;
            if ((unsigned)wi < 32u && (unsigned)hi < 32u)
                v = x[((b * 256 + c0 + ic) * 32 + hi) * 32 + wi];
            s_in2[ic][ky][wc] = make_float2(v, v);
        }
        __syncthreads();

        for (int ic = 0; ic < 32; ic++) {
            ull w2[9];
#pragma unroll
            for (int tap = 0; tap < 9; tap++)
                w2[tap] = wp[((tap * 256) + (c0 + ic)) * 128 + t];

#pragma unroll
            for (int ky = 0; ky < 3; ky++) {
                const ull* row = reinterpret_cast<const ull*>(&s_in2[ic][ky][0]);
                {
                    ull r[18];
#pragma unroll
                    for (int i = 0; i < 18; i++) r[i] = row[i];
#pragma unroll
                    for (int kx = 0; kx < 3; kx++)
#pragma unroll
                        for (int px = 0; px < 16; px++)
                            ffma2(acc[px], w2[ky * 3 + kx], r[px + kx]);
                }
                {
                    ull r[18];
#pragma unroll
                    for (int i = 0; i < 18; i++) r[i] = row[16 + i];
#pragma unroll
                    for (int kx = 0; kx < 3; kx++)
#pragma unroll
                        for (int px = 0; px < 16; px++)
                            ffma2(acc[16 + px], w2[ky * 3 + kx], r[px + kx]);
                }
            }
        }
        __syncthreads();
    }

    // writeback: channel 2t (lo halves) and 2t+1 (hi halves)
    float* out_lo = &g_act[p][((b * 256 + 2 * t) * 32 + hrow) * 32];
    float* out_hi = &g_act[p][((b * 256 + 2 * t + 1) * 32 + hrow) * 32];
    float s = 0.f, sq = 0.f;
#pragma unroll
    for (int px = 0; px < 32; px += 4) {
        float a0 = lo2(acc[px]),     b0 = hi2(acc[px]);
        float a1 = lo2(acc[px + 1]), b1 = hi2(acc[px + 1]);
        float a2 = lo2(acc[px + 2]), b2 = hi2(acc[px + 2]);
        float a3 = lo2(acc[px + 3]), b3 = hi2(acc[px + 3]);
        *reinterpret_cast<float4*>(out_lo + px) = make_float4(a0, a1, a2, a3);
        *reinterpret_cast<float4*>(out_hi + px) = make_float4(b0, b1, b2, b3);
        s  += a0 + a1 + a2 + a3 + b0 + b1 + b2 + b3;
        sq += a0*a0 + a1*a1 + a2*a2 + a3*a3 + b0*b0 + b1*b1 + b2*b2 + b3*b3;
    }

    s_r1[t] = s; s_r2[t] = sq;
    __syncthreads();
    for (int st = 64; st > 0; st >>= 1) {
        if (t < st) { s_r1[t] += s_r1[t + st]; s_r2[t] += s_r2[t + st]; }
        __syncthreads();
    }
    if (t == 0) {
        g_part[p][b][hrow][0] = s_r1[0];
        g_part[p][b][hrow][1] = s_r2[0];
    }
}

// ---------------- 3) GroupNorm(1) + exact GELU ----------------
__global__ void gn_gelu_kernel(const float* __restrict__ gq, const float* __restrict__ bq,
                               const float* __restrict__ gk, const float* __restrict__ bk,
                               const float* __restrict__ gv, const float* __restrict__ bv) {
    const int chunk = blockIdx.x;
    const int b     = blockIdx.y;
    const int p     = blockIdx.z;
    const float* gg = (p == 0) ? gq : (p == 1) ? gk : gv;
    const float* bb = (p == 0) ? bq : (p == 1) ? bk : bv;

    __shared__ float s_mu, s_rs;
    if (threadIdx.x < 32) {
        float s  = g_part[p][b][threadIdx.x][0];
        float sq = g_part[p][b][threadIdx.x][1];
#pragma unroll
        for (int o = 16; o > 0; o >>= 1) {
            s  += __shfl_down_sync(0xffffffffu, s,  o);
            sq += __shfl_down_sync(0xffffffffu, sq, o);
        }
        if (threadIdx.x == 0) {
            float mu  = s / (float)NPER;
            float var = sq / (float)NPER - mu * mu;
            s_mu = mu;
            s_rs = rsqrtf(var + 1e-6f);
        }
    }
    __syncthreads();
    const float mu = s_mu, rs = s_rs;

    float* base = &g_act[p][b * NPER + chunk * 32768];
    for (int i = threadIdx.x; i < 8192; i += 256) {
        float4 v = reinterpret_cast<float4*>(base)[i];
        int c = (chunk * 32768 + i * 4) >> 10;
        float gc = gg[c], bc = bb[c];
        float t0 = (v.x - mu) * rs * gc + bc;
        float t1 = (v.y - mu) * rs * gc + bc;
        float t2 = (v.z - mu) * rs * gc + bc;
        float t3 = (v.w - mu) * rs * gc + bc;
        v.x = 0.5f * t0 * (1.0f + erff(t0 * 0.70710678118654752f));
        v.y = 0.5f * t1 * (1.0f + erff(t1 * 0.70710678118654752f));
        v.z = 0.5f * t2 * (1.0f + erff(t2 * 0.70710678118654752f));
        v.w = 0.5f * t3 * (1.0f + erff(t3 * 0.70710678118654752f));
        reinterpret_cast<float4*>(base)[i] = v;
    }
}

// ---------------- 4) flash attention, f32x2 packed ----------------
// grid: (8 q-tiles, 8 heads, 8 batch), block 128 (one query per thread)
__global__ void __launch_bounds__(128) attn_kernel(const float* __restrict__ bias_table) {
    const int q0  = blockIdx.x * 128;
    const int h   = blockIdx.y;
    const int b   = blockIdx.z;
    const int tid = threadIdx.x;

    __shared__ __align__(16) float s_bias[BIASN + 1];  // padded to even
    __shared__ __align__(16) float s_k[32 * 128];      // 16384 B
    __shared__ __align__(16) ull   s_v2[16 * 128];     // 16384 B (d-pair interleaved)

    for (int i = tid; i < BIASN; i += 128)
        s_bias[i] = bias_table[i * HEADS + h];

    const float* aq = &g_act[0][(b * 256 + h * DHEAD) * NTOK];
    const float* ak = &g_act[1][(b * 256 + h * DHEAD) * NTOK];
    const float* av = &g_act[2][(b * 256 + h * DHEAD) * NTOK];

    const int qi = q0 + tid;
    ull q2[DHEAD];                          // dup-packed query
#pragma unroll
    for (int d = 0; d < DHEAD; d++) {
        float qv = aq[d * NTOK + qi];
        q2[d] = pack2(qv, qv);
    }

    const int yi = qi >> 5, xi = qi & 31;

    float m = -1e30f, l = 0.f;
    ull o2[16];
#pragma unroll
    for (int d2 = 0; d2 < 16; d2++) o2[d2] = 0ull;

    for (int kt = 0; kt < 8; kt++) {
        const int k0 = kt * 128;
        __syncthreads();
        for (int e = tid; e < 2048; e += 128) {
            int d2 = e >> 7, j = e & 127;
            s_k[(2 * d2) * 128 + j]     = ak[(2 * d2) * NTOK + k0 + j];
            s_k[(2 * d2 + 1) * 128 + j] = ak[(2 * d2 + 1) * NTOK + k0 + j];
            s_v2[d2 * 128 + j] = pack2(av[(2 * d2) * NTOK + k0 + j],
                                       av[(2 * d2 + 1) * NTOK + k0 + j]);
        }
        __syncthreads();

        for (int sub = 0; sub < 4; sub++) {
            const int j0 = sub * 32;
            // scores packed over key pairs, init with relative bias
            ull s2[16];
#pragma unroll
            for (int pp = 0; pp < 16; pp++) {
                int kg = k0 + j0 + 2 * pp;
                int yj = kg >> 5, xj = kg & 31;
                int idx0 = (yi - yj + 31) * 63 + (xi - xj + 31);
                int kg1 = kg + 1;
                int yj1 = kg1 >> 5, xj1 = kg1 & 31;
                int idx1 = (yi - yj1 + 31) * 63 + (xi - xj1 + 31);
                s2[pp] = pack2(s_bias[idx0], s_bias[idx1]);
            }
            // QK dot
#pragma unroll
            for (int d = 0; d < DHEAD; d++) {
                const ull* krow = reinterpret_cast<const ull*>(&s_k[d * 128 + j0]);
#pragma unroll
                for (int pp = 0; pp < 16; pp++)
                    ffma2(s2[pp], q2[d], krow[pp]);
            }
            // online softmax
            float mn = m;
#pragma unroll
            for (int pp = 0; pp < 16; pp++)
                mn = fmaxf(mn, fmaxf(lo2(s2[pp]), hi2(s2[pp])));
            const float scale = fast_exp(m - mn);
            m = mn;
            ull ls2 = 0ull;
#pragma unroll
            for (int pp = 0; pp < 16; pp++) {
                float ea = fast_exp(lo2(s2[pp]) - mn);
                float eb = fast_exp(hi2(s2[pp]) - mn);
                s2[pp] = pack2(ea, eb);
                ls2 = add2(ls2, s2[pp]);
            }
            l = l * scale + lo2(ls2) + hi2(ls2);
            const ull sc2 = pack2(scale, scale);
#pragma unroll
            for (int d2 = 0; d2 < 16; d2++) o2[d2] = mul2(o2[d2], sc2);
            // PV
#pragma unroll
            for (int jj = 0; jj < 32; jj++) {
                float pj = (jj & 1) ? hi2(s2[jj >> 1]) : lo2(s2[jj >> 1]);
                ull pj2 = pack2(pj, pj);
                const ull* vcol = &s_v2[j0 + jj];
#pragma unroll
                for (int d2 = 0; d2 < 16; d2++)
                    ffma2(o2[d2], pj2, vcol[d2 * 128]);
            }
        }
    }

    const float inv = 1.f / l;
    float* ao = &g_attn[(b * 256 + h * DHEAD) * NTOK];
#pragma unroll
    for (int d2 = 0; d2 < 16; d2++) {
        ao[(2 * d2) * NTOK + qi]     = lo2(o2[d2]) * inv;
        ao[(2 * d2 + 1) * NTOK + qi] = hi2(o2[d2]) * inv;
    }
}

// ---------------- 5) 1x1 output projection, f32x2 over pixel pairs ----------------
// grid: (32 n-tiles, 8 batch), block 256 (one oc each)
__global__ void outproj_kernel(const float* __restrict__ bo, float* __restrict__ out) {
    const int nt = blockIdx.x;
    const int b  = blockIdx.y;
    const int oc = threadIdx.x;

    __shared__ __align__(16) float s_a[256 * 32];
    for (int e = oc; e < 8192; e += 256) {
        int c = e >> 5, px = e & 31;
        s_a[e] = g_attn[(b * 256 + c) * NTOK + nt * 32 + px];
    }
    __syncthreads();

    ull acc[16];
#pragma unroll
    for (int p = 0; p < 16; p++) acc[p] = 0ull;

    for (int c = 0; c < 256; c++) {
        float wv = g_woT[c * 256 + oc];
        ull w2 = pack2(wv, wv);
        const ull* arow = reinterpret_cast<const ull*>(&s_a[c * 32]);
#pragma unroll
        for (int p = 0; p < 16; p++)
            ffma2(acc[p], w2, arow[p]);
    }

    const float bb = bo[oc];
    float* op = out + (b * 256 + oc) * NTOK + nt * 32;
#pragma unroll
    for (int p = 0; p < 16; p += 2) {
        float4 v4 = make_float4(lo2(acc[p]) + bb,     hi2(acc[p]) + bb,
                                lo2(acc[p + 1]) + bb, hi2(acc[p + 1]) + bb);
        *reinterpret_cast<float4*>(op + 2 * p) = v4;
    }
}

// ---------------- launch ----------------
extern "C" void kernel_launch(void* const* d_in, const int* in_sizes, int n_in,
                              void* d_out, int out_size) {
    const float* x  = (const float*)d_in[0];
    const float* wq = (const float*)d_in[1];
    const float* wk = (const float*)d_in[2];
    const float* wv = (const float*)d_in[3];
    const float* gq = (const float*)d_in[4];
    const float* bq = (const float*)d_in[5];
    const float* gk = (const float*)d_in[6];
    const float* bk = (const float*)d_in[7];
    const float* gv = (const float*)d_in[8];
    const float* bv = (const float*)d_in[9];
    const float* bt = (const float*)d_in[10];
    const float* wo = (const float*)d_in[11];
    const float* bo = (const float*)d_in[12];
    float* out = (float*)d_out;

    transpose_w_kernel<<<dim3((WSZ + 255) / 256, 4), 256>>>(wq, wk, wv, wo);
    conv3x3_kernel<<<dim3(32, BATCH, 3), 128>>>(x);
    gn_gelu_kernel<<<dim3(8, BATCH, 3), 256>>>(gq, bq, gk, bk, gv, bv);
    attn_kernel<<<dim3(8, HEADS, BATCH), 128>>>(bt);
    outproj_kernel<<<dim3(32, BATCH), 256>>>(bo, out);
}

// round 4
// speedup vs baseline: 1.4117x; 1.0838x over previous
#include <cuda_runtime.h>
#include <cuda_bf16.h>

typedef unsigned long long ull;

// Problem constants
#define BATCH 8
#define CHAN  256
#define HEADS 8
#define DHEAD 32
#define IH    32
#define IW    32
#define NTOK  1024
#define NPER  262144
#define WSZ   (9*256*256)
#define BIASN 3969

// ---------------- scratch ----------------
__device__ __align__(16) float g_wT[3][WSZ];            // [tap][ic][oc]
__device__ __align__(16) float g_woT[256*256];          // [c][o]
__device__ __align__(16) float g_act[3][BATCH*NPER];
__device__ __align__(16) float g_part[3][BATCH][32][2];
__device__ __align__(16) float g_attn[BATCH*NPER];

// ---------------- f32x2 helpers ----------------
__device__ __forceinline__ void ffma2(ull& d, ull a, ull b) {
    asm("fma.rn.f32x2 %0, %1, %2, %0;" : "+l"(d) : "l"(a), "l"(b));
}
__device__ __forceinline__ ull add2(ull a, ull b) {
    ull r; asm("add.rn.f32x2 %0, %1, %2;" : "=l"(r) : "l"(a), "l"(b)); return r;
}
__device__ __forceinline__ ull mul2(ull a, ull b) {
    ull r; asm("mul.rn.f32x2 %0, %1, %2;" : "=l"(r) : "l"(a), "l"(b)); return r;
}
__device__ __forceinline__ ull pack2(float a, float b) {
    ull u; asm("mov.b64 %0, {%1,%2};" : "=l"(u) : "f"(a), "f"(b)); return u;
}
__device__ __forceinline__ float lo2(ull u) { return __int_as_float((int)(unsigned)u); }
__device__ __forceinline__ float hi2(ull u) { return __int_as_float((int)(u >> 32)); }

// fast expf via exp2 poly (rel err ~1e-7); args here are always <= 0
__device__ __forceinline__ float fast_exp(float x) {
    float t  = fmaxf(x * 1.4426950408889634f, -126.0f);
    float fi = rintf(t);
    float f  = t - fi;
    float p  = 1.535336188319500e-4f;
    p = fmaf(p, f, 1.339887440266574e-3f);
    p = fmaf(p, f, 9.618437357674640e-3f);
    p = fmaf(p, f, 5.550332471162809e-2f);
    p = fmaf(p, f, 2.402264791363012e-1f);
    p = fmaf(p, f, 6.931472028550421e-1f);
    p = fmaf(p, f, 1.0f);
    return p * __int_as_float(((int)fi + 127) << 23);
}

// ---------------- 1) tiled weight transposes (coalesced both sides) ----------------
// grid (72, 8, 4), block (32, 8). p<3: conv weights [oc][ic*9+tap] -> [tap][ic][oc]
// p==3: wo [o][c] -> g_woT [c][o]
__global__ void transpose_w_kernel(const float* __restrict__ wq,
                                   const float* __restrict__ wk,
                                   const float* __restrict__ wv,
                                   const float* __restrict__ wo) {
    const int p = blockIdx.z;
    const int F = (p < 3) ? 2304 : 256;
    if ((int)blockIdx.x * 32 >= F) return;
    const float* src = (p == 0) ? wq : (p == 1) ? wk : (p == 2) ? wv : wo;

    __shared__ float tile[32][33];
    const int f0 = blockIdx.x * 32;
    const int o0 = blockIdx.y * 32;

#pragma unroll
    for (int i = 0; i < 4; i++) {
        int oc = o0 + threadIdx.y + i * 8;
        tile[threadIdx.y + i * 8][threadIdx.x] = src[oc * F + f0 + threadIdx.x];
    }
    __syncthreads();

#pragma unroll
    for (int i = 0; i < 4; i++) {
        int f  = f0 + threadIdx.y + i * 8;
        int oc = o0 + threadIdx.x;
        float v = tile[threadIdx.x][threadIdx.y + i * 8];
        if (p < 3) {
            int ic  = f / 9;
            int tap = f - ic * 9;
            g_wT[p][tap * 65536 + ic * 256 + oc] = v;
        } else {
            g_woT[f * 256 + oc] = v;
        }
    }
}

// ---------------- 2) 3x3 conv, f32x2, prefetched weights, LDS.128 rows ----------------
// grid: (32 rows, 8 batch, 3 proj), block 128 (thread t -> oc 2t, 2t+1)
__global__ void __launch_bounds__(128) conv3x3_kernel(const float* __restrict__ x) {
    const int hrow = blockIdx.x;
    const int b    = blockIdx.y;
    const int p    = blockIdx.z;
    const int t    = threadIdx.x;

    __shared__ __align__(16) float2 s_in2[32][3][34];   // dup-packed input, 26KB
    __shared__ float  s_r1[128];
    __shared__ float  s_r2[128];

    ull acc[32];
#pragma unroll
    for (int px = 0; px < 32; px++) acc[px] = 0ull;

    const ull* wp = reinterpret_cast<const ull*>(g_wT[p]);

    for (int c0 = 0; c0 < 256; c0 += 32) {
        // cooperative load: 32 ic x 3 rows x 34 cols, duplicated
        for (int e = t; e < 32 * 3 * 34; e += 128) {
            int ic = e / 102;
            int r  = e - ic * 102;
            int ky = r / 34;
            int wc = r - ky * 34;
            int wi = wc - 1;
            int hi = hrow + ky - 1;
            float v = 0.f;
            if ((unsigned)wi < 32u && (unsigned)hi < 32u)
                v = x[((b * 256 + c0 + ic) * 32 + hi) * 32 + wi];
            s_in2[ic][ky][wc] = make_float2(v, v);
        }
        __syncthreads();

        // prime weight double-buffer
        ull wcur[9];
#pragma unroll
        for (int tap = 0; tap < 9; tap++)
            wcur[tap] = wp[(tap * 256 + c0) * 128 + t];

        for (int ic = 0; ic < 32; ic++) {
            // prefetch next ic's weights (drains during the FFMA body)
            ull wnxt[9];
            const int icn = (ic + 1 < 32) ? (c0 + ic + 1) : (c0 + ic);
#pragma unroll
            for (int tap = 0; tap < 9; tap++)
                wnxt[tap] = wp[(tap * 256 + icn) * 128 + t];

#pragma unroll
            for (int ky = 0; ky < 3; ky++) {
                const ulonglong2* row2 =
                    reinterpret_cast<const ulonglong2*>(&s_in2[ic][ky][0]);
                ull r[18];
                // half A: absolute ulls 0..17
#pragma unroll
                for (int i = 0; i < 9; i++) {
                    ulonglong2 v = row2[i];
                    r[2 * i] = v.x; r[2 * i + 1] = v.y;
                }
#pragma unroll
                for (int kx = 0; kx < 3; kx++)
#pragma unroll
                    for (int px = 0; px < 16; px++)
                        ffma2(acc[px], wcur[ky * 3 + kx], r[px + kx]);
                // half B: absolute ulls 16..33  (r[j] == ull 16+j)
#pragma unroll
                for (int i = 0; i < 9; i++) {
                    ulonglong2 v = row2[8 + i];
                    r[2 * i] = v.x; r[2 * i + 1] = v.y;
                }
#pragma unroll
                for (int kx = 0; kx < 3; kx++)
#pragma unroll
                    for (int px = 0; px < 16; px++)
                        ffma2(acc[16 + px], wcur[ky * 3 + kx], r[px + kx]);
            }
#pragma unroll
            for (int tap = 0; tap < 9; tap++) wcur[tap] = wnxt[tap];
        }
        __syncthreads();
    }

    // writeback: channel 2t (lo halves) and 2t+1 (hi halves)
    float* out_lo = &g_act[p][((b * 256 + 2 * t) * 32 + hrow) * 32];
    float* out_hi = &g_act[p][((b * 256 + 2 * t + 1) * 32 + hrow) * 32];
    float s = 0.f, sq = 0.f;
#pragma unroll
    for (int px = 0; px < 32; px += 4) {
        float a0 = lo2(acc[px]),     b0 = hi2(acc[px]);
        float a1 = lo2(acc[px + 1]), b1 = hi2(acc[px + 1]);
        float a2 = lo2(acc[px + 2]), b2 = hi2(acc[px + 2]);
        float a3 = lo2(acc[px + 3]), b3 = hi2(acc[px + 3]);
        *reinterpret_cast<float4*>(out_lo + px) = make_float4(a0, a1, a2, a3);
        *reinterpret_cast<float4*>(out_hi + px) = make_float4(b0, b1, b2, b3);
        s  += a0 + a1 + a2 + a3 + b0 + b1 + b2 + b3;
        sq += a0*a0 + a1*a1 + a2*a2 + a3*a3 + b0*b0 + b1*b1 + b2*b2 + b3*b3;
    }

    s_r1[t] = s; s_r2[t] = sq;
    __syncthreads();
    for (int st = 64; st > 0; st >>= 1) {
        if (t < st) { s_r1[t] += s_r1[t + st]; s_r2[t] += s_r2[t + st]; }
        __syncthreads();
    }
    if (t == 0) {
        g_part[p][b][hrow][0] = s_r1[0];
        g_part[p][b][hrow][1] = s_r2[0];
    }
}

// ---------------- 3) GroupNorm(1) + exact GELU ----------------
__global__ void gn_gelu_kernel(const float* __restrict__ gq, const float* __restrict__ bq,
                               const float* __restrict__ gk, const float* __restrict__ bk,
                               const float* __restrict__ gv, const float* __restrict__ bv) {
    const int chunk = blockIdx.x;
    const int b     = blockIdx.y;
    const int p     = blockIdx.z;
    const float* gg = (p == 0) ? gq : (p == 1) ? gk : gv;
    const float* bb = (p == 0) ? bq : (p == 1) ? bk : bv;

    __shared__ float s_mu, s_rs;
    if (threadIdx.x < 32) {
        float s  = g_part[p][b][threadIdx.x][0];
        float sq = g_part[p][b][threadIdx.x][1];
#pragma unroll
        for (int o = 16; o > 0; o >>= 1) {
            s  += __shfl_down_sync(0xffffffffu, s,  o);
            sq += __shfl_down_sync(0xffffffffu, sq, o);
        }
        if (threadIdx.x == 0) {
            float mu  = s / (float)NPER;
            float var = sq / (float)NPER - mu * mu;
            s_mu = mu;
            s_rs = rsqrtf(var + 1e-6f);
        }
    }
    __syncthreads();
    const float mu = s_mu, rs = s_rs;

    float* base = &g_act[p][b * NPER + chunk * 32768];
    for (int i = threadIdx.x; i < 8192; i += 256) {
        float4 v = reinterpret_cast<float4*>(base)[i];
        int c = (chunk * 32768 + i * 4) >> 10;
        float gc = gg[c], bc = bb[c];
        float t0 = (v.x - mu) * rs * gc + bc;
        float t1 = (v.y - mu) * rs * gc + bc;
        float t2 = (v.z - mu) * rs * gc + bc;
        float t3 = (v.w - mu) * rs * gc + bc;
        v.x = 0.5f * t0 * (1.0f + erff(t0 * 0.70710678118654752f));
        v.y = 0.5f * t1 * (1.0f + erff(t1 * 0.70710678118654752f));
        v.z = 0.5f * t2 * (1.0f + erff(t2 * 0.70710678118654752f));
        v.w = 0.5f * t3 * (1.0f + erff(t3 * 0.70710678118654752f));
        reinterpret_cast<float4*>(base)[i] = v;
    }
}

// ---------------- 4) flash attention, f32x2, LDS.128 K and V ----------------
// grid: (8 q-tiles, 8 heads, 8 batch), block 128 (one query per thread)
// KV tile = 64 keys; V stored transposed [j][d2] with pad-stride 18.
__global__ void __launch_bounds__(128) attn_kernel(const float* __restrict__ bias_table) {
    const int q0  = blockIdx.x * 128;
    const int h   = blockIdx.y;
    const int b   = blockIdx.z;
    const int tid = threadIdx.x;

    __shared__ __align__(16) float s_bias[BIASN + 3];   // 15888 B
    __shared__ __align__(16) float s_k[32 * 64];        // 8192 B  [d][j]
    __shared__ __align__(16) ull   s_v2T[64 * 18];      // 9216 B  [j][d2] pad 18

    for (int i = tid; i < BIASN; i += 128)
        s_bias[i] = bias_table[i * HEADS + h];

    const float* aq = &g_act[0][(b * 256 + h * DHEAD) * NTOK];
    const float* ak = &g_act[1][(b * 256 + h * DHEAD) * NTOK];
    const float* av = &g_act[2][(b * 256 + h * DHEAD) * NTOK];

    const int qi = q0 + tid;
    ull q2[DHEAD];                          // dup-packed query
#pragma unroll
    for (int d = 0; d < DHEAD; d++) {
        float qv = aq[d * NTOK + qi];
        q2[d] = pack2(qv, qv);
    }

    const int yi = qi >> 5, xi = qi & 31;

    float m = -1e30f, l = 0.f;
    ull o2[16];
#pragma unroll
    for (int d2 = 0; d2 < 16; d2++) o2[d2] = 0ull;

    for (int kt = 0; kt < 16; kt++) {
        const int k0 = kt * 64;
        __syncthreads();
        for (int e = tid; e < 1024; e += 128) {
            int d2 = e >> 6, j = e & 63;
            float v0 = av[(2 * d2) * NTOK + k0 + j];
            float v1 = av[(2 * d2 + 1) * NTOK + k0 + j];
            s_k[(2 * d2) * 64 + j]     = ak[(2 * d2) * NTOK + k0 + j];
            s_k[(2 * d2 + 1) * 64 + j] = ak[(2 * d2 + 1) * NTOK + k0 + j];
            s_v2T[j * 18 + d2] = pack2(v0, v1);
        }
        __syncthreads();

        for (int sub = 0; sub < 2; sub++) {
            const int j0 = sub * 32;
            // scores packed over key pairs, init with relative bias
            ull s2[16];
#pragma unroll
            for (int pp = 0; pp < 16; pp++) {
                int kg = k0 + j0 + 2 * pp;
                int yj = kg >> 5, xj = kg & 31;
                int idx0 = (yi - yj + 31) * 63 + (xi - xj + 31);
                int kg1 = kg + 1;
                int yj1 = kg1 >> 5, xj1 = kg1 & 31;
                int idx1 = (yi - yj1 + 31) * 63 + (xi - xj1 + 31);
                s2[pp] = pack2(s_bias[idx0], s_bias[idx1]);
            }
            // QK dot, 16B K loads
#pragma unroll
            for (int d = 0; d < DHEAD; d++) {
                const ulonglong2* krow =
                    reinterpret_cast<const ulonglong2*>(&s_k[d * 64 + j0]);
#pragma unroll
                for (int pq = 0; pq < 8; pq++) {
                    ulonglong2 kk = krow[pq];
                    ffma2(s2[2 * pq],     q2[d], kk.x);
                    ffma2(s2[2 * pq + 1], q2[d], kk.y);
                }
            }
            // online softmax
            float mn = m;
#pragma unroll
            for (int pp = 0; pp < 16; pp++)
                mn = fmaxf(mn, fmaxf(lo2(s2[pp]), hi2(s2[pp])));
            const float scale = fast_exp(m - mn);
            m = mn;
            ull ls2 = 0ull;
#pragma unroll
            for (int pp = 0; pp < 16; pp++) {
                float ea = fast_exp(lo2(s2[pp]) - mn);
                float eb = fast_exp(hi2(s2[pp]) - mn);
                s2[pp] = pack2(ea, eb);
                ls2 = add2(ls2, s2[pp]);
            }
            l = l * scale + lo2(ls2) + hi2(ls2);
            const ull sc2 = pack2(scale, scale);
#pragma unroll
            for (int d2 = 0; d2 < 16; d2++) o2[d2] = mul2(o2[d2], sc2);
            // PV, 16B V loads (V transposed)
#pragma unroll
            for (int jj = 0; jj < 32; jj++) {
                float pj = (jj & 1) ? hi2(s2[jj >> 1]) : lo2(s2[jj >> 1]);
                ull pj2 = pack2(pj, pj);
                const ulonglong2* vrow =
                    reinterpret_cast<const ulonglong2*>(&s_v2T[(j0 + jj) * 18]);
#pragma unroll
                for (int q8 = 0; q8 < 8; q8++) {
                    ulonglong2 vv = vrow[q8];
                    ffma2(o2[2 * q8],     pj2, vv.x);
                    ffma2(o2[2 * q8 + 1], pj2, vv.y);
                }
            }
        }
    }

    const float inv = 1.f / l;
    float* ao = &g_attn[(b * 256 + h * DHEAD) * NTOK];
#pragma unroll
    for (int d2 = 0; d2 < 16; d2++) {
        ao[(2 * d2) * NTOK + qi]     = lo2(o2[d2]) * inv;
        ao[(2 * d2 + 1) * NTOK + qi] = hi2(o2[d2]) * inv;
    }
}

// ---------------- 5) 1x1 output projection, f32x2 + LDS.128 ----------------
// grid: (32 n-tiles, 8 batch), block 256 (one oc each)
__global__ void outproj_kernel(const float* __restrict__ bo, float* __restrict__ out) {
    const int nt = blockIdx.x;
    const int b  = blockIdx.y;
    const int oc = threadIdx.x;

    __shared__ __align__(16) float s_a[256 * 32];
    for (int e = oc; e < 8192; e += 256) {
        int c = e >> 5, px = e & 31;
        s_a[e] = g_attn[(b * 256 + c) * NTOK + nt * 32 + px];
    }
    __syncthreads();

    ull acc[16];
#pragma unroll
    for (int p = 0; p < 16; p++) acc[p] = 0ull;

    for (int c = 0; c < 256; c++) {
        float wv = g_woT[c * 256 + oc];
        ull w2 = pack2(wv, wv);
        const ulonglong2* arow2 = reinterpret_cast<const ulonglong2*>(&s_a[c * 32]);
#pragma unroll
        for (int p8 = 0; p8 < 8; p8++) {
            ulonglong2 vv = arow2[p8];
            ffma2(acc[2 * p8],     w2, vv.x);
            ffma2(acc[2 * p8 + 1], w2, vv.y);
        }
    }

    const float bb = bo[oc];
    float* op = out + (b * 256 + oc) * NTOK + nt * 32;
#pragma unroll
    for (int p = 0; p < 16; p += 2) {
        float4 v4 = make_float4(lo2(acc[p]) + bb,     hi2(acc[p]) + bb,
                                lo2(acc[p + 1]) + bb, hi2(acc[p + 1]) + bb);
        *reinterpret_cast<float4*>(op + 2 * p) = v4;
    }
}

// ---------------- launch ----------------
extern "C" void kernel_launch(void* const* d_in, const int* in_sizes, int n_in,
                              void* d_out, int out_size) {
    const float* x  = (const float*)d_in[0];
    const float* wq = (const float*)d_in[1];
    const float* wk = (const float*)d_in[2];
    const float* wv = (const float*)d_in[3];
    const float* gq = (const float*)d_in[4];
    const float* bq = (const float*)d_in[5];
    const float* gk = (const float*)d_in[6];
    const float* bk = (const float*)d_in[7];
    const float* gv = (const float*)d_in[8];
    const float* bv = (const float*)d_in[9];
    const float* bt = (const float*)d_in[10];
    const float* wo = (const float*)d_in[11];
    const float* bo = (const float*)d_in[12];
    float* out = (float*)d_out;

    transpose_w_kernel<<<dim3(72, 8, 4), dim3(32, 8)>>>(wq, wk, wv, wo);
    conv3x3_kernel<<<dim3(32, BATCH, 3), 128>>>(x);
    gn_gelu_kernel<<<dim3(8, BATCH, 3), 256>>>(gq, bq, gk, bk, gv, bv);
    attn_kernel<<<dim3(8, HEADS, BATCH), 128>>>(bt);
    outproj_kernel<<<dim3(32, BATCH), 256>>>(bo, out);
}